// round 2
// baseline (speedup 1.0000x reference)
#include <cuda_runtime.h>

#define NN 50000
#define TN 32
#define NTHREADS 256
#define HSTR 34

typedef unsigned long long u64;

__device__ __align__(256) float g_y[(size_t)NN * 512];
__device__ __align__(256) float g_WihT[128 * 512];
__device__ __align__(256) float g_WhhT[128 * 512];
__device__ __align__(256) float g_WselfT[128 * 128];
__device__ __align__(256) float g_WneighT[128 * 128];

__device__ __forceinline__ u64 pack2(float lo, float hi) {
    u64 r; asm("mov.b64 %0,{%1,%2};" : "=l"(r) : "f"(lo), "f"(hi)); return r;
}
__device__ __forceinline__ u64 pack2s(float v) { return pack2(v, v); }
__device__ __forceinline__ void unpack2(u64 v, float& lo, float& hi) {
    asm("mov.b64 {%0,%1},%2;" : "=f"(lo), "=f"(hi) : "l"(v));
}
__device__ __forceinline__ void ffma2(u64& d, u64 a, u64 b) {
    asm("fma.rn.f32x2 %0,%1,%2,%0;" : "+l"(d) : "l"(a), "l"(b));
}
__device__ __forceinline__ void cp16(float* dst, const float* src) {
    unsigned sa = (unsigned)__cvta_generic_to_shared(dst);
    asm volatile("cp.async.cg.shared.global [%0],[%1],16;" :: "r"(sa), "l"(src) : "memory");
}
__device__ __forceinline__ void cp_commit() { asm volatile("cp.async.commit_group;" ::: "memory"); }
template <int W> __device__ __forceinline__ void cp_wait() {
    asm volatile("cp.async.wait_group %0;" :: "n"(W) : "memory");
}
__device__ __forceinline__ void cp_chunk(float* dstS, const float* src, int tid) {
#pragma unroll
    for (int i = 0; i < 16; ++i) { int f4 = i * NTHREADS + tid; cp16(dstS + f4 * 4, src + f4 * 4); }
}
__device__ __forceinline__ float sigf(float v) { return __fdividef(1.f, 1.f + __expf(-v)); }
__device__ __forceinline__ float tanhf_fast(float v) { return 1.f - __fdividef(2.f, __expf(2.f * v) + 1.f); }

__device__ __forceinline__ void mma_chunk(const float* __restrict__ Wb, const float* __restrict__ act,
                                          u64* ai, u64* af, u64* ag, u64* ao, int j) {
#pragma unroll 8
    for (int kk = 0; kk < 32; ++kk) {
        const float* wr = Wb + kk * 512 + j;
        u64 wi = pack2s(wr[0]), wf = pack2s(wr[128]), wg = pack2s(wr[256]), wo = pack2s(wr[384]);
        const u64* hp = (const u64*)(act + kk * HSTR);
#pragma unroll
        for (int p = 0; p < 8; ++p) {
            u64 hv = hp[p];
            ffma2(ai[p], wi, hv); ffma2(af[p], wf, hv);
            ffma2(ag[p], wg, hv); ffma2(ao[p], wo, hv);
        }
    }
}

__device__ __forceinline__ void stage_x_tile(float* sm_x, const float* __restrict__ x, int base, int tid) {
    int node = tid >> 3, q = tid & 7, n = base + node;
#pragma unroll
    for (int u = 0; u < 4; ++u) {
        float4 v = make_float4(0.f, 0.f, 0.f, 0.f);
        if (n < NN) v = ((const float4*)(x + (size_t)n * 128))[q * 4 + u];
        int k0 = q * 16 + u * 4;
        sm_x[(k0 + 0) * HSTR + node] = v.x; sm_x[(k0 + 1) * HSTR + node] = v.y;
        sm_x[(k0 + 2) * HSTR + node] = v.z; sm_x[(k0 + 3) * HSTR + node] = v.w;
    }
}

__global__ void prep_kernel(const float* __restrict__ W_ih, const float* __restrict__ W_hh,
                            const float* __restrict__ W_self, const float* __restrict__ W_neigh) {
    int i = blockIdx.x * 256 + threadIdx.x;
    if (i < 512 * 128) {
        int g = i & 511, k = i >> 9;
        g_WihT[k * 512 + g] = W_ih[g * 128 + k];
        g_WhhT[k * 512 + g] = W_hh[g * 128 + k];
    }
    if (i < 128 * 128) {
        int jj = i & 127, k = i >> 7;
        g_WselfT[k * 128 + jj] = W_self[jj * 128 + k];
        g_WneighT[k * 128 + jj] = W_neigh[jj * 128 + k];
    }
}

// y = x @ W_ih^T + b_ih   (smem: buf0 | buf1 | sm_x)
__global__ __launch_bounds__(256, 1) void y_kernel(const float* __restrict__ x,
                                                   const float* __restrict__ b_ih) {
    extern __shared__ float smem[];
    float* buf[2] = { smem, smem + 16384 };
    float* sm_x = smem + 32768;
    const int tid = threadIdx.x, j = tid & 127, ng = tid >> 7, base = blockIdx.x * TN;

    cp_chunk(buf[0], g_WihT, tid); cp_commit();
    stage_x_tile(sm_x, x, base, tid);

    float bi = b_ih[j], bf = b_ih[128 + j], bg = b_ih[256 + j], bo = b_ih[384 + j];
    u64 ai[8], af[8], ag[8], ao[8];
#pragma unroll
    for (int p = 0; p < 8; ++p) { ai[p] = pack2s(bi); af[p] = pack2s(bf); ag[p] = pack2s(bg); ao[p] = pack2s(bo); }

    int cur = 0;
#pragma unroll 1
    for (int kc = 0; kc < 4; ++kc) {
        __syncthreads();
        if (kc < 3) { cp_chunk(buf[cur ^ 1], g_WihT + (kc + 1) * 16384, tid); cp_commit(); cp_wait<1>(); }
        else cp_wait<0>();
        __syncthreads();
        mma_chunk(buf[cur], sm_x + kc * 32 * HSTR + ng * 16, ai, af, ag, ao, j);
        cur ^= 1;
    }
#pragma unroll
    for (int p = 0; p < 8; ++p) {
        int n0 = base + ng * 16 + 2 * p, n1 = n0 + 1;
        float lo, hi;
        unpack2(ai[p], lo, hi); if (n0 < NN) g_y[(size_t)n0 * 512 + j] = lo;       if (n1 < NN) g_y[(size_t)n1 * 512 + j] = hi;
        unpack2(af[p], lo, hi); if (n0 < NN) g_y[(size_t)n0 * 512 + 128 + j] = lo; if (n1 < NN) g_y[(size_t)n1 * 512 + 128 + j] = hi;
        unpack2(ag[p], lo, hi); if (n0 < NN) g_y[(size_t)n0 * 512 + 256 + j] = lo; if (n1 < NN) g_y[(size_t)n1 * 512 + 256 + j] = hi;
        unpack2(ao[p], lo, hi); if (n0 < NN) g_y[(size_t)n0 * 512 + 384 + j] = lo; if (n1 < NN) g_y[(size_t)n1 * 512 + 384 + j] = hi;
    }
}

// smem floats: buf0[16384] buf1[16384] sm_h[4352] sm_x[4352] sm_r[4224] sm_idx[512]
#define OFF_H 32768
#define OFF_X 37120
#define OFF_R 41472
#define OFF_I 45696

__global__ __launch_bounds__(256, 1) void lstm_kernel(
    const float* __restrict__ x, const int* __restrict__ nidx,
    const float* __restrict__ b_hh, const float* __restrict__ b_self, const float* __restrict__ b_neigh,
    const float* __restrict__ g1, const float* __restrict__ bt1,
    const float* __restrict__ g3, const float* __restrict__ bt3,
    float* __restrict__ out) {
    extern __shared__ float smem[];
    float* buf[2] = { smem, smem + 16384 };
    float* sm_h = smem + OFF_H;
    float* sm_x = smem + OFF_X;
    float* sm_r = smem + OFF_R;
    int*   sm_idx = (int*)(smem + OFF_I);

    const int tid = threadIdx.x, j = tid & 127, ng = tid >> 7, base = blockIdx.x * TN;

    for (int i = tid; i < TN * 16; i += NTHREADS) {
        int n = base + (i >> 4);
        sm_idx[i] = (n < NN) ? nidx[n * 16 + (i & 15)] : 0;
    }

    float bi = b_hh[j], bf = b_hh[128 + j], bg = b_hh[256 + j], bo = b_hh[384 + j];
    float c[16];
#pragma unroll
    for (int i = 0; i < 16; ++i) c[i] = 0.f;
    u64 ai[8], af[8], ag[8], ao[8];
    __syncthreads();

#define INIT_ACC(T)                                                          \
    {                                                                        \
        _Pragma("unroll")                                                    \
        for (int p = 0; p < 8; ++p) {                                        \
            int l0 = ng * 16 + 2 * p;                                        \
            const float* y0 = g_y + (size_t)sm_idx[l0 * 16 + (T)] * 512 + j; \
            const float* y1 = g_y + (size_t)sm_idx[(l0 + 1) * 16 + (T)] * 512 + j; \
            ai[p] = pack2(y0[0] + bi,   y1[0] + bi);                         \
            af[p] = pack2(y0[128] + bf, y1[128] + bf);                       \
            ag[p] = pack2(y0[256] + bg, y1[256] + bg);                       \
            ao[p] = pack2(y0[384] + bo, y1[384] + bo);                       \
        }                                                                    \
    }

#define ACTIVATION()                                                         \
    {                                                                        \
        _Pragma("unroll")                                                    \
        for (int p = 0; p < 8; ++p) {                                        \
            float i0, i1, f0, f1, q0, q1, o0, o1;                            \
            unpack2(ai[p], i0, i1); unpack2(af[p], f0, f1);                  \
            unpack2(ag[p], q0, q1); unpack2(ao[p], o0, o1);                  \
            float c0 = sigf(f0) * c[2 * p]     + sigf(i0) * tanhf_fast(q0);  \
            float c1 = sigf(f1) * c[2 * p + 1] + sigf(i1) * tanhf_fast(q1);  \
            c[2 * p] = c0; c[2 * p + 1] = c1;                                \
            *(u64*)(sm_h + j * HSTR + ng * 16 + 2 * p) =                     \
                pack2(sigf(o0) * tanhf_fast(c0), sigf(o1) * tanhf_fast(c1)); \
        }                                                                    \
    }

    INIT_ACC(0);
    ACTIVATION();
    cp_chunk(buf[0], g_WhhT, tid); cp_commit();

    int cur = 0;
#pragma unroll 1
    for (int t = 1; t < 16; ++t) {
        INIT_ACC(t);
#pragma unroll 1
        for (int kc = 0; kc < 4; ++kc) {
            __syncthreads();
            const float* nsrc = (kc < 3) ? (g_WhhT + (kc + 1) * 16384)
                                         : ((t < 15) ? g_WhhT : g_WselfT);
            cp_chunk(buf[cur ^ 1], nsrc, tid); cp_commit();
            cp_wait<1>();
            __syncthreads();
            mma_chunk(buf[cur], sm_h + kc * 32 * HSTR + ng * 16, ai, af, ag, ao, j);
            cur ^= 1;
        }
        __syncthreads();   // all reads of sm_h / buf done before overwrite
        ACTIVATION();
    }
    // buf[0] <- W_selfT in flight (committed at t=15,kc=3); buf[1] free.
    cp_chunk(buf[1], g_WneighT, tid); cp_commit();
    stage_x_tile(sm_x, x, base, tid);
    cp_wait<0>();
    __syncthreads();   // buf0=WselfT, buf1=WneighT, sm_x staged, sm_h final visible

    // r = x@Wself^T + h@Wneigh^T + (b_self+b_neigh)
    float bsn = b_self[j] + b_neigh[j];
    u64 racc[8];
#pragma unroll
    for (int p = 0; p < 8; ++p) racc[p] = pack2s(bsn);
#pragma unroll 4
    for (int k = 0; k < 128; ++k) {
        u64 ws = pack2s(buf[0][k * 128 + j]);
        u64 wn = pack2s(buf[1][k * 128 + j]);
        const u64* xp = (const u64*)(sm_x + k * HSTR + ng * 16);
        const u64* hp = (const u64*)(sm_h + k * HSTR + ng * 16);
#pragma unroll
        for (int p = 0; p < 8; ++p) { ffma2(racc[p], ws, xp[p]); ffma2(racc[p], wn, hp[p]); }
    }
#pragma unroll
    for (int p = 0; p < 8; ++p) {
        float lo, hi; unpack2(racc[p], lo, hi);
        int node = ng * 16 + 2 * p;
        sm_r[node * 132 + j] = lo;
        sm_r[(node + 1) * 132 + j] = hi;
    }
    __syncthreads();

    // LN -> leaky -> +x -> LN -> leaky.  warp w handles nodes w*4..w*4+3
    int w = tid >> 5, l = tid & 31;
    float4 gv1 = *(const float4*)(g1 + l * 4), bv1 = *(const float4*)(bt1 + l * 4);
    float4 gv3 = *(const float4*)(g3 + l * 4), bv3 = *(const float4*)(bt3 + l * 4);
#pragma unroll 1
    for (int q = 0; q < 4; ++q) {
        int node = w * 4 + q, n = base + node;
        if (n >= NN) break;
        float4 rv = *(float4*)(sm_r + node * 132 + l * 4);
        float4 xv = *(const float4*)(x + (size_t)n * 128 + l * 4);
        float s1 = rv.x + rv.y + rv.z + rv.w;
        float s2 = rv.x * rv.x + rv.y * rv.y + rv.z * rv.z + rv.w * rv.w;
#pragma unroll
        for (int m = 16; m > 0; m >>= 1) { s1 += __shfl_xor_sync(~0u, s1, m); s2 += __shfl_xor_sync(~0u, s2, m); }
        float mu = s1 * 0.0078125f;
        float rs = rsqrtf(s2 * 0.0078125f - mu * mu + 1e-5f);
        float4 h;
        h.x = (rv.x - mu) * rs * gv1.x + bv1.x; h.y = (rv.y - mu) * rs * gv1.y + bv1.y;
        h.z = (rv.z - mu) * rs * gv1.z + bv1.z; h.w = (rv.w - mu) * rs * gv1.w + bv1.w;
        h.x = fmaxf(h.x, 0.01f * h.x) + xv.x; h.y = fmaxf(h.y, 0.01f * h.y) + xv.y;
        h.z = fmaxf(h.z, 0.01f * h.z) + xv.z; h.w = fmaxf(h.w, 0.01f * h.w) + xv.w;
        s1 = h.x + h.y + h.z + h.w;
        s2 = h.x * h.x + h.y * h.y + h.z * h.z + h.w * h.w;
#pragma unroll
        for (int m = 16; m > 0; m >>= 1) { s1 += __shfl_xor_sync(~0u, s1, m); s2 += __shfl_xor_sync(~0u, s2, m); }
        mu = s1 * 0.0078125f;
        rs = rsqrtf(s2 * 0.0078125f - mu * mu + 1e-5f);
        float4 o;
        o.x = (h.x - mu) * rs * gv3.x + bv3.x; o.y = (h.y - mu) * rs * gv3.y + bv3.y;
        o.z = (h.z - mu) * rs * gv3.z + bv3.z; o.w = (h.w - mu) * rs * gv3.w + bv3.w;
        o.x = fmaxf(o.x, 0.01f * o.x); o.y = fmaxf(o.y, 0.01f * o.y);
        o.z = fmaxf(o.z, 0.01f * o.z); o.w = fmaxf(o.w, 0.01f * o.w);
        *(float4*)(out + (size_t)n * 128 + l * 4) = o;
    }
}

extern "C" void kernel_launch(void* const* d_in, const int* in_sizes, int n_in,
                              void* d_out, int out_size) {
    const float* x       = (const float*)d_in[0];
    const int*   nidx    = (const int*)d_in[1];
    const float* W_self  = (const float*)d_in[2];
    const float* b_self  = (const float*)d_in[3];
    const float* W_neigh = (const float*)d_in[4];
    const float* b_neigh = (const float*)d_in[5];
    const float* W_ih    = (const float*)d_in[6];
    const float* W_hh    = (const float*)d_in[7];
    const float* b_ih    = (const float*)d_in[8];
    const float* b_hh    = (const float*)d_in[9];
    const float* g1      = (const float*)d_in[10];
    const float* bt1     = (const float*)d_in[11];
    const float* g3      = (const float*)d_in[12];
    const float* bt3     = (const float*)d_in[13];
    float* out = (float*)d_out;

    cudaFuncSetAttribute(y_kernel, cudaFuncAttributeMaxDynamicSharedMemorySize, 148480);
    cudaFuncSetAttribute(lstm_kernel, cudaFuncAttributeMaxDynamicSharedMemorySize, 184832);

    int blocks = (NN + TN - 1) / TN;
    prep_kernel<<<256, 256>>>(W_ih, W_hh, W_self, W_neigh);
    y_kernel<<<blocks, 256, 148480>>>(x, b_ih);
    lstm_kernel<<<blocks, 256, 184832>>>(x, nidx, b_hh, b_self, b_neigh, g1, bt1, g3, bt3, out);
}

// round 3
// speedup vs baseline: 1.0001x; 1.0001x over previous
#include <cuda_runtime.h>

#define NN 50000
#define TN 32
#define NTHREADS 256
#define HSTR 34

typedef unsigned long long u64;

__device__ __align__(256) float g_y[(size_t)NN * 512];
__device__ __align__(256) float g_WihT[128 * 512];
__device__ __align__(256) float g_WhhT[128 * 512];
__device__ __align__(256) float g_WselfT[128 * 128];
__device__ __align__(256) float g_WneighT[128 * 128];

__device__ __forceinline__ u64 pack2(float lo, float hi) {
    u64 r; asm("mov.b64 %0,{%1,%2};" : "=l"(r) : "f"(lo), "f"(hi)); return r;
}
__device__ __forceinline__ u64 pack2s(float v) { return pack2(v, v); }
__device__ __forceinline__ void unpack2(u64 v, float& lo, float& hi) {
    asm("mov.b64 {%0,%1},%2;" : "=f"(lo), "=f"(hi) : "l"(v));
}
__device__ __forceinline__ void ffma2(u64& d, u64 a, u64 b) {
    asm("fma.rn.f32x2 %0,%1,%2,%0;" : "+l"(d) : "l"(a), "l"(b));
}
__device__ __forceinline__ void cp16(float* dst, const float* src) {
    unsigned sa = (unsigned)__cvta_generic_to_shared(dst);
    asm volatile("cp.async.cg.shared.global [%0],[%1],16;" :: "r"(sa), "l"(src) : "memory");
}
__device__ __forceinline__ void cp_commit() { asm volatile("cp.async.commit_group;" ::: "memory"); }
template <int W> __device__ __forceinline__ void cp_wait() {
    asm volatile("cp.async.wait_group %0;" :: "n"(W) : "memory");
}
__device__ __forceinline__ void cp_chunk(float* dstS, const float* src, int tid) {
#pragma unroll
    for (int i = 0; i < 16; ++i) { int f4 = i * NTHREADS + tid; cp16(dstS + f4 * 4, src + f4 * 4); }
}
__device__ __forceinline__ float sigf(float v) { return __fdividef(1.f, 1.f + __expf(-v)); }
__device__ __forceinline__ float tanhf_fast(float v) { return 1.f - __fdividef(2.f, __expf(2.f * v) + 1.f); }

__device__ __forceinline__ void mma_chunk(const float* __restrict__ Wb, const float* __restrict__ act,
                                          u64* ai, u64* af, u64* ag, u64* ao, int j) {
#pragma unroll 8
    for (int kk = 0; kk < 32; ++kk) {
        const float* wr = Wb + kk * 512 + j;
        u64 wi = pack2s(wr[0]), wf = pack2s(wr[128]), wg = pack2s(wr[256]), wo = pack2s(wr[384]);
        const u64* hp = (const u64*)(act + kk * HSTR);
#pragma unroll
        for (int p = 0; p < 8; ++p) {
            u64 hv = hp[p];
            ffma2(ai[p], wi, hv); ffma2(af[p], wf, hv);
            ffma2(ag[p], wg, hv); ffma2(ao[p], wo, hv);
        }
    }
}

__device__ __forceinline__ void stage_x_tile(float* sm_x, const float* __restrict__ x, int base, int tid) {
    int node = tid >> 3, q = tid & 7, n = base + node;
#pragma unroll
    for (int u = 0; u < 4; ++u) {
        float4 v = make_float4(0.f, 0.f, 0.f, 0.f);
        if (n < NN) v = ((const float4*)(x + (size_t)n * 128))[q * 4 + u];
        int k0 = q * 16 + u * 4;
        sm_x[(k0 + 0) * HSTR + node] = v.x; sm_x[(k0 + 1) * HSTR + node] = v.y;
        sm_x[(k0 + 2) * HSTR + node] = v.z; sm_x[(k0 + 3) * HSTR + node] = v.w;
    }
}

__global__ void prep_kernel(const float* __restrict__ W_ih, const float* __restrict__ W_hh,
                            const float* __restrict__ W_self, const float* __restrict__ W_neigh) {
    int i = blockIdx.x * 256 + threadIdx.x;
    if (i < 512 * 128) {
        int g = i & 511, k = i >> 9;
        g_WihT[k * 512 + g] = W_ih[g * 128 + k];
        g_WhhT[k * 512 + g] = W_hh[g * 128 + k];
    }
    if (i < 128 * 128) {
        int jj = i & 127, k = i >> 7;
        g_WselfT[k * 128 + jj] = W_self[jj * 128 + k];
        g_WneighT[k * 128 + jj] = W_neigh[jj * 128 + k];
    }
}

// y = x @ W_ih^T + b_ih   (smem: buf0 | buf1 | sm_x)
__global__ __launch_bounds__(256, 1) void y_kernel(const float* __restrict__ x,
                                                   const float* __restrict__ b_ih) {
    extern __shared__ float smem[];
    float* buf[2] = { smem, smem + 16384 };
    float* sm_x = smem + 32768;
    const int tid = threadIdx.x, j = tid & 127, ng = tid >> 7, base = blockIdx.x * TN;

    cp_chunk(buf[0], g_WihT, tid); cp_commit();
    stage_x_tile(sm_x, x, base, tid);

    float bi = b_ih[j], bf = b_ih[128 + j], bg = b_ih[256 + j], bo = b_ih[384 + j];
    u64 ai[8], af[8], ag[8], ao[8];
#pragma unroll
    for (int p = 0; p < 8; ++p) { ai[p] = pack2s(bi); af[p] = pack2s(bf); ag[p] = pack2s(bg); ao[p] = pack2s(bo); }

    int cur = 0;
#pragma unroll 1
    for (int kc = 0; kc < 4; ++kc) {
        __syncthreads();
        if (kc < 3) { cp_chunk(buf[cur ^ 1], g_WihT + (kc + 1) * 16384, tid); cp_commit(); cp_wait<1>(); }
        else cp_wait<0>();
        __syncthreads();
        mma_chunk(buf[cur], sm_x + kc * 32 * HSTR + ng * 16, ai, af, ag, ao, j);
        cur ^= 1;
    }
#pragma unroll
    for (int p = 0; p < 8; ++p) {
        int n0 = base + ng * 16 + 2 * p, n1 = n0 + 1;
        float lo, hi;
        unpack2(ai[p], lo, hi); if (n0 < NN) g_y[(size_t)n0 * 512 + j] = lo;       if (n1 < NN) g_y[(size_t)n1 * 512 + j] = hi;
        unpack2(af[p], lo, hi); if (n0 < NN) g_y[(size_t)n0 * 512 + 128 + j] = lo; if (n1 < NN) g_y[(size_t)n1 * 512 + 128 + j] = hi;
        unpack2(ag[p], lo, hi); if (n0 < NN) g_y[(size_t)n0 * 512 + 256 + j] = lo; if (n1 < NN) g_y[(size_t)n1 * 512 + 256 + j] = hi;
        unpack2(ao[p], lo, hi); if (n0 < NN) g_y[(size_t)n0 * 512 + 384 + j] = lo; if (n1 < NN) g_y[(size_t)n1 * 512 + 384 + j] = hi;
    }
}

// smem floats: buf0[16384] buf1[16384] sm_h[4352] sm_x[4352] sm_r[4224] sm_idx[512]
#define OFF_H 32768
#define OFF_X 37120
#define OFF_R 41472
#define OFF_I 45696

__global__ __launch_bounds__(256, 1) void lstm_kernel(
    const float* __restrict__ x, const int* __restrict__ nidx,
    const float* __restrict__ b_hh, const float* __restrict__ b_self, const float* __restrict__ b_neigh,
    const float* __restrict__ g1, const float* __restrict__ bt1,
    const float* __restrict__ g3, const float* __restrict__ bt3,
    float* __restrict__ out) {
    extern __shared__ float smem[];
    float* buf[2] = { smem, smem + 16384 };
    float* sm_h = smem + OFF_H;
    float* sm_x = smem + OFF_X;
    float* sm_r = smem + OFF_R;
    int*   sm_idx = (int*)(smem + OFF_I);

    const int tid = threadIdx.x, j = tid & 127, ng = tid >> 7, base = blockIdx.x * TN;

    for (int i = tid; i < TN * 16; i += NTHREADS) {
        int n = base + (i >> 4);
        sm_idx[i] = (n < NN) ? nidx[n * 16 + (i & 15)] : 0;
    }

    float bi = b_hh[j], bf = b_hh[128 + j], bg = b_hh[256 + j], bo = b_hh[384 + j];
    float c[16];
#pragma unroll
    for (int i = 0; i < 16; ++i) c[i] = 0.f;
    u64 ai[8], af[8], ag[8], ao[8];
    __syncthreads();

#define INIT_ACC(T)                                                          \
    {                                                                        \
        _Pragma("unroll")                                                    \
        for (int p = 0; p < 8; ++p) {                                        \
            int l0 = ng * 16 + 2 * p;                                        \
            const float* y0 = g_y + (size_t)sm_idx[l0 * 16 + (T)] * 512 + j; \
            const float* y1 = g_y + (size_t)sm_idx[(l0 + 1) * 16 + (T)] * 512 + j; \
            ai[p] = pack2(y0[0] + bi,   y1[0] + bi);                         \
            af[p] = pack2(y0[128] + bf, y1[128] + bf);                       \
            ag[p] = pack2(y0[256] + bg, y1[256] + bg);                       \
            ao[p] = pack2(y0[384] + bo, y1[384] + bo);                       \
        }                                                                    \
    }

#define ACTIVATION()                                                         \
    {                                                                        \
        _Pragma("unroll")                                                    \
        for (int p = 0; p < 8; ++p) {                                        \
            float i0, i1, f0, f1, q0, q1, o0, o1;                            \
            unpack2(ai[p], i0, i1); unpack2(af[p], f0, f1);                  \
            unpack2(ag[p], q0, q1); unpack2(ao[p], o0, o1);                  \
            float c0 = sigf(f0) * c[2 * p]     + sigf(i0) * tanhf_fast(q0);  \
            float c1 = sigf(f1) * c[2 * p + 1] + sigf(i1) * tanhf_fast(q1);  \
            c[2 * p] = c0; c[2 * p + 1] = c1;                                \
            *(u64*)(sm_h + j * HSTR + ng * 16 + 2 * p) =                     \
                pack2(sigf(o0) * tanhf_fast(c0), sigf(o1) * tanhf_fast(c1)); \
        }                                                                    \
    }

    INIT_ACC(0);
    ACTIVATION();
    cp_chunk(buf[0], g_WhhT, tid); cp_commit();

    int cur = 0;
#pragma unroll 1
    for (int t = 1; t < 16; ++t) {
        INIT_ACC(t);
#pragma unroll 1
        for (int kc = 0; kc < 4; ++kc) {
            __syncthreads();
            const float* nsrc = (kc < 3) ? (g_WhhT + (kc + 1) * 16384)
                                         : ((t < 15) ? g_WhhT : g_WselfT);
            cp_chunk(buf[cur ^ 1], nsrc, tid); cp_commit();
            cp_wait<1>();
            __syncthreads();
            mma_chunk(buf[cur], sm_h + kc * 32 * HSTR + ng * 16, ai, af, ag, ao, j);
            cur ^= 1;
        }
        __syncthreads();   // all reads of sm_h / buf done before overwrite
        ACTIVATION();
    }
    // buf[0] <- W_selfT in flight (committed at t=15,kc=3); buf[1] free.
    cp_chunk(buf[1], g_WneighT, tid); cp_commit();
    stage_x_tile(sm_x, x, base, tid);
    cp_wait<0>();
    __syncthreads();   // buf0=WselfT, buf1=WneighT, sm_x staged, sm_h final visible

    // r = x@Wself^T + h@Wneigh^T + (b_self+b_neigh)
    float bsn = b_self[j] + b_neigh[j];
    u64 racc[8];
#pragma unroll
    for (int p = 0; p < 8; ++p) racc[p] = pack2s(bsn);
#pragma unroll 4
    for (int k = 0; k < 128; ++k) {
        u64 ws = pack2s(buf[0][k * 128 + j]);
        u64 wn = pack2s(buf[1][k * 128 + j]);
        const u64* xp = (const u64*)(sm_x + k * HSTR + ng * 16);
        const u64* hp = (const u64*)(sm_h + k * HSTR + ng * 16);
#pragma unroll
        for (int p = 0; p < 8; ++p) { ffma2(racc[p], ws, xp[p]); ffma2(racc[p], wn, hp[p]); }
    }
#pragma unroll
    for (int p = 0; p < 8; ++p) {
        float lo, hi; unpack2(racc[p], lo, hi);
        int node = ng * 16 + 2 * p;
        sm_r[node * 132 + j] = lo;
        sm_r[(node + 1) * 132 + j] = hi;
    }
    __syncthreads();

    // LN -> leaky -> +x -> LN -> leaky.  warp w handles nodes w*4..w*4+3
    int w = tid >> 5, l = tid & 31;
    float4 gv1 = *(const float4*)(g1 + l * 4), bv1 = *(const float4*)(bt1 + l * 4);
    float4 gv3 = *(const float4*)(g3 + l * 4), bv3 = *(const float4*)(bt3 + l * 4);
#pragma unroll 1
    for (int q = 0; q < 4; ++q) {
        int node = w * 4 + q, n = base + node;
        if (n >= NN) break;
        float4 rv = *(float4*)(sm_r + node * 132 + l * 4);
        float4 xv = *(const float4*)(x + (size_t)n * 128 + l * 4);
        float s1 = rv.x + rv.y + rv.z + rv.w;
        float s2 = rv.x * rv.x + rv.y * rv.y + rv.z * rv.z + rv.w * rv.w;
#pragma unroll
        for (int m = 16; m > 0; m >>= 1) { s1 += __shfl_xor_sync(~0u, s1, m); s2 += __shfl_xor_sync(~0u, s2, m); }
        float mu = s1 * 0.0078125f;
        float rs = rsqrtf(s2 * 0.0078125f - mu * mu + 1e-5f);
        float4 h;
        h.x = (rv.x - mu) * rs * gv1.x + bv1.x; h.y = (rv.y - mu) * rs * gv1.y + bv1.y;
        h.z = (rv.z - mu) * rs * gv1.z + bv1.z; h.w = (rv.w - mu) * rs * gv1.w + bv1.w;
        h.x = fmaxf(h.x, 0.01f * h.x) + xv.x; h.y = fmaxf(h.y, 0.01f * h.y) + xv.y;
        h.z = fmaxf(h.z, 0.01f * h.z) + xv.z; h.w = fmaxf(h.w, 0.01f * h.w) + xv.w;
        s1 = h.x + h.y + h.z + h.w;
        s2 = h.x * h.x + h.y * h.y + h.z * h.z + h.w * h.w;
#pragma unroll
        for (int m = 16; m > 0; m >>= 1) { s1 += __shfl_xor_sync(~0u, s1, m); s2 += __shfl_xor_sync(~0u, s2, m); }
        mu = s1 * 0.0078125f;
        rs = rsqrtf(s2 * 0.0078125f - mu * mu + 1e-5f);
        float4 o;
        o.x = (h.x - mu) * rs * gv3.x + bv3.x; o.y = (h.y - mu) * rs * gv3.y + bv3.y;
        o.z = (h.z - mu) * rs * gv3.z + bv3.z; o.w = (h.w - mu) * rs * gv3.w + bv3.w;
        o.x = fmaxf(o.x, 0.01f * o.x); o.y = fmaxf(o.y, 0.01f * o.y);
        o.z = fmaxf(o.z, 0.01f * o.z); o.w = fmaxf(o.w, 0.01f * o.w);
        *(float4*)(out + (size_t)n * 128 + l * 4) = o;
    }
}

extern "C" void kernel_launch(void* const* d_in, const int* in_sizes, int n_in,
                              void* d_out, int out_size) {
    const float* x       = (const float*)d_in[0];
    const int*   nidx    = (const int*)d_in[1];
    const float* W_self  = (const float*)d_in[2];
    const float* b_self  = (const float*)d_in[3];
    const float* W_neigh = (const float*)d_in[4];
    const float* b_neigh = (const float*)d_in[5];
    const float* W_ih    = (const float*)d_in[6];
    const float* W_hh    = (const float*)d_in[7];
    const float* b_ih    = (const float*)d_in[8];
    const float* b_hh    = (const float*)d_in[9];
    const float* g1      = (const float*)d_in[10];
    const float* bt1     = (const float*)d_in[11];
    const float* g3      = (const float*)d_in[12];
    const float* bt3     = (const float*)d_in[13];
    float* out = (float*)d_out;

    cudaFuncSetAttribute(y_kernel, cudaFuncAttributeMaxDynamicSharedMemorySize, 148480);
    cudaFuncSetAttribute(lstm_kernel, cudaFuncAttributeMaxDynamicSharedMemorySize, 184832);

    int blocks = (NN + TN - 1) / TN;
    prep_kernel<<<256, 256>>>(W_ih, W_hh, W_self, W_neigh);
    y_kernel<<<blocks, 256, 148480>>>(x, b_ih);
    lstm_kernel<<<blocks, 256, 184832>>>(x, nidx, b_hh, b_self, b_neigh, g1, bt1, g3, bt3, out);
}